// round 15
// baseline (speedup 1.0000x reference)
#include <cuda_runtime.h>
#include <cstdint>

#define MBLK    64
#define PDIM    256
#define ROWLEN  16384
#define KTOT    768
#define BK      32
#define NT      24            // K tiles
#define STAGES  3
#define A_BYTES 24576         // 192 rows x 128B
#define B_BYTES 32768         // 256 rows x 128B
#define STAGE_BYTES (A_BYTES + B_BYTES)        // 57344
#define SMEM_BYTES  (STAGES * STAGE_BYTES)     // 172032 -> 1 CTA/SM
#define THREADS 384
#define MTILES  22            // ceil(4096/192)

// repacked weights [i][q][768], tf32-rounded, truncation-compensated,
// k-permuted within 8-groups as [0,4,1,5,2,6,3,7] for LDS.64 fragments
__device__ float g_w[(size_t)MBLK * PDIM * KTOT];

// ---------- weight repack (vectorized, one 8-float group per thread) ----------
__global__ void cvt_w_kernel(const float* __restrict__ Wd,
                             const float* __restrict__ Wu,
                             const float* __restrict__ Wl,
                             const float* __restrict__ Wtr,
                             const float* __restrict__ Wbl) {
    const int gidx = blockIdx.x * blockDim.x + threadIdx.x;
    const int GPI = PDIM * KTOT / 8;     // 24576
    if (gidx >= MBLK * GPI) return;
    const int i  = gidx / GPI;
    const int r  = gidx - i * GPI;
    const int q  = r / 96;
    const int kg = r - q * 96;
    const int seg = kg >> 5;
    const int p8  = (kg & 31) << 3;

    const float* src;
    if (seg == 0) {
        src = (i == 0) ? Wtr : Wl + (size_t)(i - 1) * PDIM * PDIM;
    } else if (seg == 1) {
        src = Wd + (size_t)i * PDIM * PDIM;
    } else {
        src = (i == MBLK - 1) ? Wbl : Wu + (size_t)i * PDIM * PDIM;
    }
    src += (size_t)q * PDIM + p8;

    float4 lo = *reinterpret_cast<const float4*>(src);
    float4 hi = *reinterpret_cast<const float4*>(src + 4);

    const float comp = 1.00048828125f;   // 1 + 2^-11 (raw-A truncation comp)
    float v[8] = { lo.x, hi.x, lo.y, hi.y, lo.z, hi.z, lo.w, hi.w };
    uint32_t u[8];
#pragma unroll
    for (int j = 0; j < 8; j++) {
        float t = v[j] * comp;
        asm("cvt.rna.tf32.f32 %0, %1;" : "=r"(u[j]) : "f"(t));
    }
    float4* dst = reinterpret_cast<float4*>(g_w + (size_t)gidx * 8);
    dst[0] = make_float4(__uint_as_float(u[0]), __uint_as_float(u[1]),
                         __uint_as_float(u[2]), __uint_as_float(u[3]));
    dst[1] = make_float4(__uint_as_float(u[4]), __uint_as_float(u[5]),
                         __uint_as_float(u[6]), __uint_as_float(u[7]));
}

// ---------- tf32 legacy-HMMA GEMM ----------
// Grid (22 mb, 64 i), 384 threads, CTA tile 192x256x32,
// 12 warps 3x4 (warp tile 64x64) -> 3 warps/SMSP with 3-stage ring kept.
// A raw fp32 (HW tf32-truncation, compensated in W); B frags via LDS.64.
// Last M tile: loads row-clamped, stores guarded.
__global__ void __launch_bounds__(THREADS, 1)
bxd_gemm(const float* __restrict__ x, float* __restrict__ out) {
    extern __shared__ char smem[];
    uint32_t sbase;
    asm("{ .reg .u64 t; cvta.to.shared.u64 t, %1; cvt.u32.u64 %0, t; }"
        : "=r"(sbase) : "l"(smem));

    const int tid = threadIdx.x;
    const int mb = blockIdx.x;   // M tile 0..21 (192 rows each)
    const int i  = blockIdx.y;   // block row 0..63

    const int warp = tid >> 5, lane = tid & 31;
    const int wr = warp >> 2, wc = warp & 3;   // 3x4 warp grid
    const int g  = lane >> 2, tg = lane & 3;

    int jcol[3];
    jcol[0] = (i + MBLK - 1) & (MBLK - 1);
    jcol[1] = i;
    jcol[2] = (i + 1) & (MBLK - 1);

    // ---- cp.async lanes
    const int lrow = tid >> 3;   // A: 0..47; B uses tid<256 -> 0..31
    const int lk4  = tid & 7;
    const int chk  = ((lk4 ^ (lrow & 7)) << 4);
    const int arow0 = mb * 192 + lrow;          // + t*48, clamped
    const float* gB = g_w + (size_t)(i * 256 + lrow) * KTOT + lk4 * 4;
    const uint32_t sA = sbase + lrow * 128 + chk;
    const uint32_t sB = sA + A_BYTES;           // same lrow/chk for tid<256

    // ---- fragment bases (immediates for mf/nf minimize regs)
    const uint32_t aBase = (wr * 64 + g) * 128 + tg * 4;             // +mf*2048 (+1024)
    const uint32_t bBase = A_BYTES + (wc * 64 + g) * 128 + (tg & 1) * 8;  // +nf*1024

    float acc[4][8][4];
#pragma unroll
    for (int mf = 0; mf < 4; mf++)
#pragma unroll
        for (int nf = 0; nf < 8; nf++)
#pragma unroll
            for (int c = 0; c < 4; c++) acc[mf][nf][c] = 0.0f;

    uint32_t a[4][4], b[8][2];

    auto issue_A = [&](int kt) {
        const uint32_t st = (kt % STAGES) * STAGE_BYTES;
        const int ka = jcol[kt >> 3] * PDIM + (kt & 7) * BK + lk4 * 4;
#pragma unroll
        for (int t = 0; t < 4; t++) {
            int grow = arow0 + t * 48;
            grow = grow < 4095 ? grow : 4095;   // clamp last tile
            asm volatile("cp.async.cg.shared.global [%0], [%1], 16;"
                         :: "r"(sA + st + t * 48 * 128),
                            "l"(x + (size_t)grow * ROWLEN + ka));
        }
    };
    auto issue_B = [&](int kt) {
        if (tid < 256) {
            const uint32_t st = (kt % STAGES) * STAGE_BYTES;
            const float* b0 = gB + kt * BK;
#pragma unroll
            for (int t = 0; t < 8; t++)
                asm volatile("cp.async.cg.shared.global [%0], [%1], 16;"
                             :: "r"(sB + st + t * 32 * 128),
                                "l"(b0 + (size_t)t * 32 * KTOT));
        }
    };

    auto load_frags = [&](uint32_t st, int ks) {
        const uint32_t c0 = (((2 * ks) ^ g) << 4);
        const uint32_t c1 = (((2 * ks + 1) ^ g) << 4);
        const uint32_t a0 = st + aBase + c0;
        const uint32_t a1 = st + aBase + c1;
        // A: raw fp32 bits (HW truncates to tf32; compensated in W)
#pragma unroll
        for (int mf = 0; mf < 4; mf++) {
            asm volatile("ld.shared.b32 %0, [%1];" : "=r"(a[mf][0]) : "r"(a0 + mf * 2048));
            asm volatile("ld.shared.b32 %0, [%1];" : "=r"(a[mf][1]) : "r"(a0 + mf * 2048 + 1024));
            asm volatile("ld.shared.b32 %0, [%1];" : "=r"(a[mf][2]) : "r"(a1 + mf * 2048));
            asm volatile("ld.shared.b32 %0, [%1];" : "=r"(a[mf][3]) : "r"(a1 + mf * 2048 + 1024));
        }
        // B: one LDS.64 per nf (k-permuted layout: {k=tg, k=tg+4} contiguous)
        const uint32_t bb = st + bBase + (((2 * ks + (tg >> 1)) ^ g) << 4);
#pragma unroll
        for (int nf = 0; nf < 8; nf++)
            asm volatile("ld.shared.v2.b32 {%0, %1}, [%2];"
                         : "=r"(b[nf][0]), "=r"(b[nf][1])
                         : "r"(bb + nf * 1024));
    };

    issue_A(0); issue_B(0);
    asm volatile("cp.async.commit_group;");
    issue_A(1); issue_B(1);
    asm volatile("cp.async.commit_group;");

    for (int kt = 0; kt < NT; kt++) {
        asm volatile("cp.async.wait_group 1;");
        __syncthreads();

        const uint32_t st = sbase + (kt % STAGES) * STAGE_BYTES;
        const bool pre = (kt + 2 < NT);

#pragma unroll
        for (int ks = 0; ks < 4; ks++) {
            load_frags(st, ks);
            if (ks == 1 && pre) issue_A(kt + 2);
            if (ks == 2 && pre) issue_B(kt + 2);
#pragma unroll
            for (int mf = 0; mf < 4; mf++)
#pragma unroll
                for (int nf = 0; nf < 8; nf++) {
                    float* c = acc[mf][nf];
                    asm volatile(
                        "mma.sync.aligned.m16n8k8.row.col.f32.tf32.tf32.f32 "
                        "{%0,%1,%2,%3}, {%4,%5,%6,%7}, {%8,%9}, {%0,%1,%2,%3};\n"
                        : "+f"(c[0]), "+f"(c[1]), "+f"(c[2]), "+f"(c[3])
                        : "r"(a[mf][0]), "r"(a[mf][1]), "r"(a[mf][2]), "r"(a[mf][3]),
                          "r"(b[nf][0]), "r"(b[nf][1]));
                }
        }
        asm volatile("cp.async.commit_group;");
    }

    // epilogue: guarded float2 stores (fragment layout (g, 2tg))
    if (mb < MTILES - 1 || wr == 0) {
        float* obase = out + (size_t)(mb * 192 + wr * 64 + g) * ROWLEN
                     + (size_t)i * PDIM + wc * 64 + tg * 2;
#pragma unroll
        for (int mf = 0; mf < 4; mf++) {
#pragma unroll
            for (int nf = 0; nf < 8; nf++) {
                float2 v0 = make_float2(acc[mf][nf][0], acc[mf][nf][1]);
                float2 v1 = make_float2(acc[mf][nf][2], acc[mf][nf][3]);
                *reinterpret_cast<float2*>(obase + (size_t)(mf * 16) * ROWLEN + nf * 8) = v0;
                *reinterpret_cast<float2*>(obase + (size_t)(mf * 16 + 8) * ROWLEN + nf * 8) = v1;
            }
        }
    }
}

// ---------------- launcher ----------------
extern "C" void kernel_launch(void* const* d_in, const int* in_sizes, int n_in,
                              void* d_out, int out_size) {
    const float* x   = (const float*)d_in[0];
    const float* Wd  = (const float*)d_in[1];
    const float* Wu  = (const float*)d_in[2];
    const float* Wl  = (const float*)d_in[3];
    const float* Wtr = (const float*)d_in[4];
    const float* Wbl = (const float*)d_in[5];
    float* out = (float*)d_out;

    cvt_w_kernel<<<6144, 256>>>(Wd, Wu, Wl, Wtr, Wbl);

    (void)cudaFuncSetAttribute(bxd_gemm,
                               cudaFuncAttributeMaxDynamicSharedMemorySize,
                               SMEM_BYTES);
    bxd_gemm<<<dim3(MTILES, 64), THREADS, SMEM_BYTES>>>(x, out);
}

// round 16
// speedup vs baseline: 1.5635x; 1.5635x over previous
#include <cuda_runtime.h>
#include <cstdint>

#define MBLK    64
#define PDIM    256
#define ROWLEN  16384
#define KTOT    768
#define BK      32
#define NT      24            // K tiles
#define STAGES  3
#define A_BYTES 16384         // 128 rows x 128B
#define B_BYTES 32768         // 256 rows x 128B
#define STAGE_BYTES (A_BYTES + B_BYTES)        // 49152
#define SMEM_BYTES  (STAGES * STAGE_BYTES)     // 147456 -> 1 CTA/SM
#define THREADS 256

// repacked weights [i][q][768], tf32-rounded, truncation-compensated,
// k-permuted within 8-groups as [0,4,1,5,2,6,3,7] for LDS.64 fragments
__device__ float g_w[(size_t)MBLK * PDIM * KTOT];

// ---------- weight repack (vectorized, one 8-float group per thread) ----------
__global__ void cvt_w_kernel(const float* __restrict__ Wd,
                             const float* __restrict__ Wu,
                             const float* __restrict__ Wl,
                             const float* __restrict__ Wtr,
                             const float* __restrict__ Wbl) {
    const int gidx = blockIdx.x * blockDim.x + threadIdx.x;
    const int GPI = PDIM * KTOT / 8;     // 24576
    if (gidx >= MBLK * GPI) return;
    const int i  = gidx / GPI;
    const int r  = gidx - i * GPI;
    const int q  = r / 96;
    const int kg = r - q * 96;
    const int seg = kg >> 5;
    const int p8  = (kg & 31) << 3;

    const float* src;
    if (seg == 0) {
        src = (i == 0) ? Wtr : Wl + (size_t)(i - 1) * PDIM * PDIM;
    } else if (seg == 1) {
        src = Wd + (size_t)i * PDIM * PDIM;
    } else {
        src = (i == MBLK - 1) ? Wbl : Wu + (size_t)i * PDIM * PDIM;
    }
    src += (size_t)q * PDIM + p8;

    float4 lo = *reinterpret_cast<const float4*>(src);
    float4 hi = *reinterpret_cast<const float4*>(src + 4);

    const float comp = 1.00048828125f;   // 1 + 2^-11 (raw-A truncation comp)
    float v[8] = { lo.x, hi.x, lo.y, hi.y, lo.z, hi.z, lo.w, hi.w };
    uint32_t u[8];
#pragma unroll
    for (int j = 0; j < 8; j++) {
        float t = v[j] * comp;
        asm("cvt.rna.tf32.f32 %0, %1;" : "=r"(u[j]) : "f"(t));
    }
    float4* dst = reinterpret_cast<float4*>(g_w + (size_t)gidx * 8);
    dst[0] = make_float4(__uint_as_float(u[0]), __uint_as_float(u[1]),
                         __uint_as_float(u[2]), __uint_as_float(u[3]));
    dst[1] = make_float4(__uint_as_float(u[4]), __uint_as_float(u[5]),
                         __uint_as_float(u[6]), __uint_as_float(u[7]));
}

// ---------- tf32 legacy-HMMA GEMM ----------
// Grid (32 mb, 64 i), 256 threads, CTA tile 128x256x32,
// 8 warps 2x4 (warp tile 64x64) -> 2 warps/SMSP, 3-stage cp.async ring
// (48KB/stage), 1 CTA/SM. Per-warp inner loop identical to R14 champion:
// A raw fp32 LDS.32 (HW tf32-truncation, compensated in W),
// B k-permuted LDS.64, 16B XOR swizzle, double-buffered fragments.
__global__ void __launch_bounds__(THREADS, 1)
bxd_gemm(const float* __restrict__ x, float* __restrict__ out) {
    extern __shared__ char smem[];
    uint32_t sbase;
    asm("{ .reg .u64 t; cvta.to.shared.u64 t, %1; cvt.u32.u64 %0, t; }"
        : "=r"(sbase) : "l"(smem));

    const int tid = threadIdx.x;
    const int mb = blockIdx.x;   // batch tile 0..31 (128 rows)
    const int i  = blockIdx.y;   // block row 0..63

    const int warp = tid >> 5, lane = tid & 31;
    const int wr = warp >> 2, wc = warp & 3;   // 2x4 warp grid
    const int g  = lane >> 2, tg = lane & 3;

    int jcol[3];
    jcol[0] = (i + MBLK - 1) & (MBLK - 1);
    jcol[1] = i;
    jcol[2] = (i + 1) & (MBLK - 1);

    // ---- cp.async lanes: lrow 0..31, lk4 = 16B chunk 0..7
    const int lrow = tid >> 3;
    const int lk4  = tid & 7;
    const int chk  = ((lk4 ^ (lrow & 7)) << 4);
    const float* gA = x + (size_t)(mb * 128 + lrow) * ROWLEN + lk4 * 4;
    const float* gB = g_w + (size_t)(i * 256 + lrow) * KTOT + lk4 * 4;
    const uint32_t sA = sbase + lrow * 128 + chk;
    const uint32_t sB = sA + A_BYTES;

    // ---- fragment read byte offsets (within stage)
    uint32_t aRow[4][2], bRow[8];
#pragma unroll
    for (int mf = 0; mf < 4; mf++) {
        aRow[mf][0] = (wr * 64 + mf * 16 + g) * 128 + tg * 4;
        aRow[mf][1] = aRow[mf][0] + 8 * 128;
    }
    // B: LDS.64 base; chunk per ks: ((2ks + (tg>>1)) ^ g)*16 + (tg&1)*8
#pragma unroll
    for (int nf = 0; nf < 8; nf++)
        bRow[nf] = A_BYTES + (wc * 64 + nf * 8 + g) * 128 + (tg & 1) * 8;

    float acc[4][8][4];
#pragma unroll
    for (int mf = 0; mf < 4; mf++)
#pragma unroll
        for (int nf = 0; nf < 8; nf++)
#pragma unroll
            for (int c = 0; c < 4; c++) acc[mf][nf][c] = 0.0f;

    uint32_t a[2][4][4], b[2][8][2];

    auto issue_A = [&](int kt) {
        const uint32_t st = (kt % STAGES) * STAGE_BYTES;
        const float* a0 = gA + jcol[kt >> 3] * PDIM + (kt & 7) * BK;
#pragma unroll
        for (int t = 0; t < 4; t++)
            asm volatile("cp.async.cg.shared.global [%0], [%1], 16;"
                         :: "r"(sA + st + t * 32 * 128),
                            "l"(a0 + (size_t)t * 32 * ROWLEN));
    };
    auto issue_B = [&](int kt) {
        const uint32_t st = (kt % STAGES) * STAGE_BYTES;
        const float* b0 = gB + kt * BK;
#pragma unroll
        for (int t = 0; t < 8; t++)
            asm volatile("cp.async.cg.shared.global [%0], [%1], 16;"
                         :: "r"(sB + st + t * 32 * 128),
                            "l"(b0 + (size_t)t * 32 * KTOT));
    };

    auto load_frags = [&](uint32_t st, int ks, int buf) {
        const uint32_t c0 = (((2 * ks) ^ g) << 4);
        const uint32_t c1 = (((2 * ks + 1) ^ g) << 4);
        // A: raw fp32 bits (HW truncates to tf32; compensated in W)
#pragma unroll
        for (int mf = 0; mf < 4; mf++) {
            asm volatile("ld.shared.b32 %0, [%1];" : "=r"(a[buf][mf][0]) : "r"(st + aRow[mf][0] + c0));
            asm volatile("ld.shared.b32 %0, [%1];" : "=r"(a[buf][mf][1]) : "r"(st + aRow[mf][1] + c0));
            asm volatile("ld.shared.b32 %0, [%1];" : "=r"(a[buf][mf][2]) : "r"(st + aRow[mf][0] + c1));
            asm volatile("ld.shared.b32 %0, [%1];" : "=r"(a[buf][mf][3]) : "r"(st + aRow[mf][1] + c1));
        }
        // B: one LDS.64 per nf (k-permuted layout: {k=tg, k=tg+4} contiguous)
        const uint32_t bc = (((2 * ks + (tg >> 1)) ^ g) << 4);
#pragma unroll
        for (int nf = 0; nf < 8; nf++)
            asm volatile("ld.shared.v2.b32 {%0, %1}, [%2];"
                         : "=r"(b[buf][nf][0]), "=r"(b[buf][nf][1])
                         : "r"(st + bRow[nf] + bc));
    };

    issue_A(0); issue_B(0);
    asm volatile("cp.async.commit_group;");
    issue_A(1); issue_B(1);
    asm volatile("cp.async.commit_group;");

    for (int kt = 0; kt < NT; kt++) {
        asm volatile("cp.async.wait_group 1;");
        __syncthreads();

        const uint32_t st = sbase + (kt % STAGES) * STAGE_BYTES;
        const bool pre = (kt + 2 < NT);

        load_frags(st, 0, 0);
#pragma unroll
        for (int ks = 0; ks < 4; ks++) {
            // interleave next-tile global loads under tensor-busy windows
            if (ks == 1 && pre) issue_A(kt + 2);
            if (ks == 2 && pre) issue_B(kt + 2);
            if (ks < 3) load_frags(st, ks + 1, (ks + 1) & 1);
            const int cur = ks & 1;
#pragma unroll
            for (int mf = 0; mf < 4; mf++)
#pragma unroll
                for (int nf = 0; nf < 8; nf++) {
                    float* c = acc[mf][nf];
                    asm volatile(
                        "mma.sync.aligned.m16n8k8.row.col.f32.tf32.tf32.f32 "
                        "{%0,%1,%2,%3}, {%4,%5,%6,%7}, {%8,%9}, {%0,%1,%2,%3};\n"
                        : "+f"(c[0]), "+f"(c[1]), "+f"(c[2]), "+f"(c[3])
                        : "r"(a[cur][mf][0]), "r"(a[cur][mf][1]),
                          "r"(a[cur][mf][2]), "r"(a[cur][mf][3]),
                          "r"(b[cur][nf][0]), "r"(b[cur][nf][1]));
                }
        }
        asm volatile("cp.async.commit_group;");
    }

    // epilogue: direct float2 stores (fragment layout (g, 2tg))
    size_t obase = (size_t)(mb * 128 + wr * 64) * ROWLEN
                 + (size_t)i * PDIM + wc * 64;
#pragma unroll
    for (int mf = 0; mf < 4; mf++) {
#pragma unroll
        for (int nf = 0; nf < 8; nf++) {
            int row = mf * 16 + g;
            int col = nf * 8 + tg * 2;
            float2 v0 = make_float2(acc[mf][nf][0], acc[mf][nf][1]);
            float2 v1 = make_float2(acc[mf][nf][2], acc[mf][nf][3]);
            *reinterpret_cast<float2*>(out + obase + (size_t)row * ROWLEN + col) = v0;
            *reinterpret_cast<float2*>(out + obase + (size_t)(row + 8) * ROWLEN + col) = v1;
        }
    }
}

// ---------------- launcher ----------------
extern "C" void kernel_launch(void* const* d_in, const int* in_sizes, int n_in,
                              void* d_out, int out_size) {
    const float* x   = (const float*)d_in[0];
    const float* Wd  = (const float*)d_in[1];
    const float* Wu  = (const float*)d_in[2];
    const float* Wl  = (const float*)d_in[3];
    const float* Wtr = (const float*)d_in[4];
    const float* Wbl = (const float*)d_in[5];
    float* out = (float*)d_out;

    cvt_w_kernel<<<6144, 256>>>(Wd, Wu, Wl, Wtr, Wbl);

    (void)cudaFuncSetAttribute(bxd_gemm,
                               cudaFuncAttributeMaxDynamicSharedMemorySize,
                               SMEM_BYTES);
    bxd_gemm<<<dim3(32, 64), THREADS, SMEM_BYTES>>>(x, out);
}

// round 17
// speedup vs baseline: 1.7894x; 1.1445x over previous
#include <cuda_runtime.h>
#include <cstdint>

#define MBLK    64
#define PDIM    256
#define ROWLEN  16384
#define KTOT    768
#define BK      32
#define NT      24          // K tiles (= 8 x 3-stage rounds)
#define STAGES  3
#define STAGE_BYTES 32768   // A 16KB + B 16KB, swizzled
#define SMEM_BYTES  (STAGES * STAGE_BYTES)   // 98304 -> 2 CTAs/SM

// repacked weights [i][q][768], tf32-rounded, truncation-compensated,
// k-permuted within 8-groups as [0,4,1,5,2,6,3,7] for LDS.64 fragments
__device__ float g_w[(size_t)MBLK * PDIM * KTOT];

// ---------- weight repack (vectorized, one 8-float group per thread) ----------
__global__ void cvt_w_kernel(const float* __restrict__ Wd,
                             const float* __restrict__ Wu,
                             const float* __restrict__ Wl,
                             const float* __restrict__ Wtr,
                             const float* __restrict__ Wbl) {
    const int gidx = blockIdx.x * blockDim.x + threadIdx.x;
    const int GPI = PDIM * KTOT / 8;     // 24576
    if (gidx >= MBLK * GPI) return;
    const int i  = gidx / GPI;
    const int r  = gidx - i * GPI;
    const int q  = r / 96;
    const int kg = r - q * 96;
    const int seg = kg >> 5;
    const int p8  = (kg & 31) << 3;

    const float* src;
    if (seg == 0) {
        src = (i == 0) ? Wtr : Wl + (size_t)(i - 1) * PDIM * PDIM;
    } else if (seg == 1) {
        src = Wd + (size_t)i * PDIM * PDIM;
    } else {
        src = (i == MBLK - 1) ? Wbl : Wu + (size_t)i * PDIM * PDIM;
    }
    src += (size_t)q * PDIM + p8;

    float4 lo = *reinterpret_cast<const float4*>(src);
    float4 hi = *reinterpret_cast<const float4*>(src + 4);

    const float comp = 1.00048828125f;   // 1 + 2^-11 (raw-A truncation comp)
    float v[8] = { lo.x, hi.x, lo.y, hi.y, lo.z, hi.z, lo.w, hi.w };
    uint32_t u[8];
#pragma unroll
    for (int j = 0; j < 8; j++) {
        float t = v[j] * comp;
        asm("cvt.rna.tf32.f32 %0, %1;" : "=r"(u[j]) : "f"(t));
    }
    float4* dst = reinterpret_cast<float4*>(g_w + (size_t)gidx * 8);
    dst[0] = make_float4(__uint_as_float(u[0]), __uint_as_float(u[1]),
                         __uint_as_float(u[2]), __uint_as_float(u[3]));
    dst[1] = make_float4(__uint_as_float(u[4]), __uint_as_float(u[5]),
                         __uint_as_float(u[6]), __uint_as_float(u[7]));
}

// ---------- tf32 legacy-HMMA GEMM (R14 champion + kt-loop unroll x3) ----------
// Grid (32 mb, 2 nb, 64 i), 128 threads, CTA tile 128x128x32,
// 4 warps 2x2 (64x64), 3-stage cp.async ring, XOR swizzle, 2 CTAs/SM.
// A fed raw (HW tf32-truncation, compensated in W); B frags via LDS.64.
// Outer loop unrolled by STAGES so stage offsets are immediates.
__global__ void __launch_bounds__(128, 2)
bxd_gemm(const float* __restrict__ x, float* __restrict__ out) {
    extern __shared__ char smem[];
    uint32_t sbase;
    asm("{ .reg .u64 t; cvta.to.shared.u64 t, %1; cvt.u32.u64 %0, t; }"
        : "=r"(sbase) : "l"(smem));

    const int tid = threadIdx.x;
    const int mb = blockIdx.x;   // batch tile 0..31
    const int nb = blockIdx.y;   // n tile 0..1
    const int i  = blockIdx.z;   // block row 0..63

    const int warp = tid >> 5, lane = tid & 31;
    const int wr = warp >> 1, wc = warp & 1;
    const int g  = lane >> 2, tg = lane & 3;

    int jcol[3];
    jcol[0] = (i + MBLK - 1) & (MBLK - 1);
    jcol[1] = i;
    jcol[2] = (i + 1) & (MBLK - 1);

    // ---- cp.async lanes
    const int lrow = tid >> 3;
    const int lk4  = tid & 7;
    const int chk  = ((lk4 ^ (lrow & 7)) << 4);
    const float* gA = x + (size_t)(mb * 128 + lrow) * ROWLEN + lk4 * 4;
    const float* gB = g_w + (size_t)(i * 256 + nb * 128 + lrow) * KTOT + lk4 * 4;
    const uint32_t sA = sbase + lrow * 128 + chk;
    const uint32_t sB = sA + 16384;

    // ---- fragment read byte offsets (within stage)
    uint32_t aRow[4][2], bRow[8];
#pragma unroll
    for (int mf = 0; mf < 4; mf++) {
        aRow[mf][0] = (wr * 64 + mf * 16 + g) * 128 + tg * 4;
        aRow[mf][1] = aRow[mf][0] + 8 * 128;
    }
    // B: LDS.64 base; chunk per ks: ((2ks + (tg>>1)) ^ g)*16 + (tg&1)*8
#pragma unroll
    for (int nf = 0; nf < 8; nf++)
        bRow[nf] = 16384 + (wc * 64 + nf * 8 + g) * 128 + (tg & 1) * 8;

    float acc[4][8][4];
#pragma unroll
    for (int mf = 0; mf < 4; mf++)
#pragma unroll
        for (int nf = 0; nf < 8; nf++)
#pragma unroll
            for (int c = 0; c < 4; c++) acc[mf][nf][c] = 0.0f;

    uint32_t a[2][4][4], b[2][8][2];

    auto issue_A = [&](int kt, uint32_t st) {
        const float* a0 = gA + jcol[kt >> 3] * PDIM + (kt & 7) * BK;
#pragma unroll
        for (int t = 0; t < 8; t++)
            asm volatile("cp.async.cg.shared.global [%0], [%1], 16;"
                         :: "r"(sA + st + t * 16 * 128),
                            "l"(a0 + (size_t)t * 16 * ROWLEN));
    };
    auto issue_B = [&](int kt, uint32_t st) {
        const float* b0 = gB + kt * BK;
#pragma unroll
        for (int t = 0; t < 8; t++)
            asm volatile("cp.async.cg.shared.global [%0], [%1], 16;"
                         :: "r"(sB + st + t * 16 * 128),
                            "l"(b0 + (size_t)t * 16 * KTOT));
    };

    auto load_frags = [&](uint32_t st, int ks, int buf) {
        const uint32_t c0 = (((2 * ks) ^ g) << 4);
        const uint32_t c1 = (((2 * ks + 1) ^ g) << 4);
        // A: raw fp32 bits (HW truncates to tf32; compensated in W)
#pragma unroll
        for (int mf = 0; mf < 4; mf++) {
            asm volatile("ld.shared.b32 %0, [%1];" : "=r"(a[buf][mf][0]) : "r"(st + aRow[mf][0] + c0));
            asm volatile("ld.shared.b32 %0, [%1];" : "=r"(a[buf][mf][1]) : "r"(st + aRow[mf][1] + c0));
            asm volatile("ld.shared.b32 %0, [%1];" : "=r"(a[buf][mf][2]) : "r"(st + aRow[mf][0] + c1));
            asm volatile("ld.shared.b32 %0, [%1];" : "=r"(a[buf][mf][3]) : "r"(st + aRow[mf][1] + c1));
        }
        // B: one LDS.64 per nf (k-permuted layout: {k=tg, k=tg+4} contiguous)
        const uint32_t bc = (((2 * ks + (tg >> 1)) ^ g) << 4);
#pragma unroll
        for (int nf = 0; nf < 8; nf++)
            asm volatile("ld.shared.v2.b32 {%0, %1}, [%2];"
                         : "=r"(b[buf][nf][0]), "=r"(b[buf][nf][1])
                         : "r"(st + bRow[nf] + bc));
    };

    issue_A(0, 0); issue_B(0, 0);
    asm volatile("cp.async.commit_group;");
    issue_A(1, STAGE_BYTES); issue_B(1, STAGE_BYTES);
    asm volatile("cp.async.commit_group;");

#pragma unroll 1
    for (int kr = 0; kr < NT / STAGES; kr++) {
#pragma unroll
        for (int s = 0; s < STAGES; s++) {
            const int kt = kr * STAGES + s;
            asm volatile("cp.async.wait_group 1;");
            __syncthreads();

            const uint32_t st = sbase + s * STAGE_BYTES;   // immediate per body
            const bool pre = (kt + 2 < NT);

            load_frags(st, 0, 0);
#pragma unroll
            for (int ks = 0; ks < 4; ks++) {
                // interleave next-tile global loads under tensor-busy windows
                if (ks == 1 && pre) issue_A(kt + 2, ((s + 2) % STAGES) * STAGE_BYTES);
                if (ks == 2 && pre) issue_B(kt + 2, ((s + 2) % STAGES) * STAGE_BYTES);
                if (ks < 3) load_frags(st, ks + 1, (ks + 1) & 1);
                const int cur = ks & 1;
#pragma unroll
                for (int mf = 0; mf < 4; mf++)
#pragma unroll
                    for (int nf = 0; nf < 8; nf++) {
                        float* c = acc[mf][nf];
                        asm volatile(
                            "mma.sync.aligned.m16n8k8.row.col.f32.tf32.tf32.f32 "
                            "{%0,%1,%2,%3}, {%4,%5,%6,%7}, {%8,%9}, {%0,%1,%2,%3};\n"
                            : "+f"(c[0]), "+f"(c[1]), "+f"(c[2]), "+f"(c[3])
                            : "r"(a[cur][mf][0]), "r"(a[cur][mf][1]),
                              "r"(a[cur][mf][2]), "r"(a[cur][mf][3]),
                              "r"(b[cur][nf][0]), "r"(b[cur][nf][1]));
                    }
            }
            asm volatile("cp.async.commit_group;");
        }
    }

    // epilogue: direct float2 stores (fragment layout (g, 2tg))
    size_t obase = (size_t)(mb * 128 + wr * 64) * ROWLEN
                 + (size_t)i * PDIM + nb * 128 + wc * 64;
#pragma unroll
    for (int mf = 0; mf < 4; mf++) {
#pragma unroll
        for (int nf = 0; nf < 8; nf++) {
            int row = mf * 16 + g;
            int col = nf * 8 + tg * 2;
            float2 v0 = make_float2(acc[mf][nf][0], acc[mf][nf][1]);
            float2 v1 = make_float2(acc[mf][nf][2], acc[mf][nf][3]);
            *reinterpret_cast<float2*>(out + obase + (size_t)row * ROWLEN + col) = v0;
            *reinterpret_cast<float2*>(out + obase + (size_t)(row + 8) * ROWLEN + col) = v1;
        }
    }
}

// ---------------- launcher ----------------
extern "C" void kernel_launch(void* const* d_in, const int* in_sizes, int n_in,
                              void* d_out, int out_size) {
    const float* x   = (const float*)d_in[0];
    const float* Wd  = (const float*)d_in[1];
    const float* Wu  = (const float*)d_in[2];
    const float* Wl  = (const float*)d_in[3];
    const float* Wtr = (const float*)d_in[4];
    const float* Wbl = (const float*)d_in[5];
    float* out = (float*)d_out;

    // 64*24576 groups / 512 threads = 3072 blocks
    cvt_w_kernel<<<3072, 512>>>(Wd, Wu, Wl, Wtr, Wbl);

    (void)cudaFuncSetAttribute(bxd_gemm,
                               cudaFuncAttributeMaxDynamicSharedMemorySize,
                               SMEM_BYTES);
    bxd_gemm<<<dim3(32, 2, 64), 128, SMEM_BYTES>>>(x, out);
}